// round 14
// baseline (speedup 1.0000x reference)
#include <cuda_runtime.h>
#include <cstdint>

#define BDIM 256
#define NROWS 4096
#define DCOLS 8192
#define SPLIT 4                                  // blocks per row
#define SEG_FLOATS (DCOLS / SPLIT)               // 2048 floats per segment
#define NBLOCKS (NROWS * SPLIT)                  // 16384
#define ITERS (SEG_FLOATS / 4 / BDIM)            // 2 float4-iters per thread

__device__ __forceinline__ float smoothl1(float a, float b) {
    float d = a - b;
    float ad = fabsf(d);
    return (ad < 1.0f) ? (0.5f * d * d) : (ad - 0.5f);
}

__global__ void zero_out_kernel(float* __restrict__ out) {
    out[0] = 0.0f;
}

__global__ __launch_bounds__(BDIM)
void mask_smoothl1_seg_kernel(const float* __restrict__ in,
                              const float* __restrict__ tgt,
                              const int* __restrict__ mask,
                              float* __restrict__ out) {
    const int bid = blockIdx.x;
    const int tid = threadIdx.x;
    const int row = bid >> 2;          // bid / SPLIT
    const int seg = bid & (SPLIT - 1);

    const int m = mask[row];
    if (m == 0) return;                // whole row inactive

    const size_t base = (size_t)row * DCOLS + (size_t)seg * SEG_FLOATS;
    const float4* __restrict__ A = reinterpret_cast<const float4*>(in  + base);
    const float4* __restrict__ B = reinterpret_cast<const float4*>(tgt + base);

    float acc0 = 0.0f, acc1 = 0.0f;
    #pragma unroll
    for (int it = 0; it < ITERS; ++it) {
        const int i = it * BDIM + tid;
        const float4 x = A[i];
        const float4 y = B[i];
        acc0 += smoothl1(x.x, y.x);
        acc1 += smoothl1(x.y, y.y);
        acc0 += smoothl1(x.z, y.z);
        acc1 += smoothl1(x.w, y.w);
    }
    float acc = acc0 + acc1;

    // block reduce
    #pragma unroll
    for (int off = 16; off > 0; off >>= 1)
        acc += __shfl_xor_sync(0xFFFFFFFFu, acc, off);

    __shared__ float warp_sums[BDIM / 32];
    const int wid = tid >> 5;
    const int lid = tid & 31;
    if (lid == 0) warp_sums[wid] = acc;
    __syncthreads();

    if (tid == 0) {
        float v = 0.0f;
        #pragma unroll
        for (int w = 0; w < BDIM / 32; ++w) v += warp_sums[w];
        // fire-and-forget reduction (REDG.F32); order wobble ~1e-6 rel
        atomicAdd(out, v * ((float)m / (float)DCOLS));
    }
}

extern "C" void kernel_launch(void* const* d_in, const int* in_sizes, int n_in,
                              void* d_out, int out_size) {
    const float* inputs  = (const float*)d_in[0];
    const float* targets = (const float*)d_in[1];
    const int*   mask    = (const int*)d_in[2];
    float* out = (float*)d_out;

    zero_out_kernel<<<1, 1>>>(out);
    mask_smoothl1_seg_kernel<<<NBLOCKS, BDIM>>>(inputs, targets, mask, out);
}